// round 6
// baseline (speedup 1.0000x reference)
#include <cuda_runtime.h>
#include <cstdint>

#define B_SZ 512
#define I_SZ 256
#define H_SZ 512
#define ICH  8

// Transformed parameter planes (recurrent + sensory) and scratch
__device__ float g_SG[H_SZ*H_SZ];
__device__ float g_MS[H_SZ*H_SZ];
__device__ float g_WE[H_SZ*H_SZ];
__device__ float g_WW[H_SZ*H_SZ];
__device__ float s_SG[I_SZ*H_SZ];
__device__ float s_MS[I_SZ*H_SZ];
__device__ float s_WE[I_SZ*H_SZ];
__device__ float s_WW[I_SZ*H_SZ];
__device__ float g_CN[H_SZ];
__device__ float g_CD[H_SZ];
__device__ float g_A [B_SZ*H_SZ];
__device__ float g_Dc[B_SZ*H_SZ];
__device__ float g_v0[B_SZ*H_SZ];
__device__ float g_v1[B_SZ*H_SZ];

// Two tanh for the price of one MUFU op: pack f32 pair -> f16x2, MUFU.TANH, unpack.
__device__ __forceinline__ void tanh2_fast(float a0, float a1, float& t0, float& t1){
    uint32_t p, t;
    asm("cvt.rn.f16x2.f32 %0, %1, %2;" : "=r"(p) : "f"(a1), "f"(a0));  // hi=a1, lo=a0
    asm("tanh.approx.f16x2 %0, %1;" : "=r"(t) : "r"(p));
    asm("{ .reg .b16 lo, hi;\n\t"
        "  mov.b32 {lo, hi}, %2;\n\t"
        "  cvt.f32.f16 %0, lo;\n\t"
        "  cvt.f32.f16 %1, hi; }"
        : "=f"(t0), "=f"(t1) : "r"(t));
}

// sigmoid((v-mu)*sigma) = 0.5*tanh(0.5*sigma*v - 0.5*sigma*mu) + 0.5
__global__ void k_prep(const float* __restrict__ mu, const float* __restrict__ sigma,
                       const float* __restrict__ W,  const float* __restrict__ erev,
                       const float* __restrict__ smu, const float* __restrict__ ssig,
                       const float* __restrict__ sW,  const float* __restrict__ serev){
    int idx = blockIdx.x*blockDim.x + threadIdx.x;
    if (idx < H_SZ*H_SZ){
        float s = sigma[idx], m = mu[idx], w = W[idx], e = erev[idx];
        g_SG[idx] = 0.5f*s;
        g_MS[idx] = -0.5f*s*m;
        g_WE[idx] = 0.5f*w*e;
        g_WW[idx] = 0.5f*w;
    } else if (idx < (H_SZ + I_SZ)*H_SZ){
        int j = idx - H_SZ*H_SZ;
        float s = ssig[j], m = smu[j], w = sW[j], e = serev[j];
        s_SG[j] = 0.5f*s;
        s_MS[j] = -0.5f*s*m;
        s_WE[j] = 0.5f*w*e;
        s_WW[j] = 0.5f*w;
    }
}

// Per-h constants: column sums of WE/WW over recurrent (H) + sensory (I) rows
__global__ void k_colsum(){
    int h0 = blockIdx.x * 32;
    int hh = threadIdx.x & 31;
    int it = threadIdx.x >> 5;
    float sn = 0.f, sd = 0.f;
    for (int i = it; i < H_SZ; i += 8){
        sn += g_WE[i*H_SZ + h0 + hh];
        sd += g_WW[i*H_SZ + h0 + hh];
    }
    for (int i = it; i < I_SZ; i += 8){
        sn += s_WE[i*H_SZ + h0 + hh];
        sd += s_WW[i*H_SZ + h0 + hh];
    }
    __shared__ float rn[8][32], rd[8][32];
    rn[it][hh] = sn; rd[it][hh] = sd;
    __syncthreads();
    if (it == 0){
        float a = 0.f, b = 0.f;
        #pragma unroll
        for (int k = 0; k < 8; k++){ a += rn[k][hh]; b += rd[k][hh]; }
        g_CN[h0+hh] = a; g_CD[h0+hh] = b;
    }
}

// ---------------------------------------------------------------------------
// Main loop core, i-split within block.
// 256 threads = 2 halves x 4 warps. Tile 64h x 16b. Half hf reduces
// i in [hf*HALF_I, (hf+1)*HALF_I). Lane covers h = h0+2*lane+{0,1}.
// Warp-in-half covers 4 batches. Register double-buffer, 1 barrier/chunk.
// tanh pairs go through MUFU as f16x2 (2 results / MUFU op).
// ---------------------------------------------------------------------------
template<int HALF_I, int VSTR>
__device__ __forceinline__ void mainloop_core(
        const float* __restrict__ P0, const float* __restrict__ P1,
        const float* __restrict__ P2, const float* __restrict__ P3,
        const float* __restrict__ vin, int h0, int b0, int tx,
        float (&num)[4][2], float (&den)[4][2],
        float (*sp)[2][4][ICH][64], float (*vs)[2][16][ICH+1])
{
    const int hf   = tx >> 7;          // half: 0/1
    const int txh  = tx & 127;
    const int lane = tx & 31;
    const int wq   = (txh >> 5);       // warp in half: 0..3
    const int ibase = hf * HALF_I;
    const int pic  = txh >> 4;         // 0..7   (prefetch ic)
    const int pq   = (txh & 15) * 4;   // 0..60  (prefetch h-quad)
    const int vrow = txh >> 3;         // 0..15
    const int vq   = txh & 7;          // 0..7
    const int NC   = HALF_I / ICH;

    float4 r[4];
    float rv;

    auto prefetch = [&](int c){
        int i0 = ibase + c * ICH;
        int g  = (i0 + pic)*H_SZ + h0 + pq;
        r[0] = *(const float4*)&P0[g];
        r[1] = *(const float4*)&P1[g];
        r[2] = *(const float4*)&P2[g];
        r[3] = *(const float4*)&P3[g];
        rv   = vin[(b0 + vrow)*VSTR + i0 + vq];
    };
    auto sts = [&](int buf){
        *(float4*)&sp[hf][buf][0][pic][pq] = r[0];
        *(float4*)&sp[hf][buf][1][pic][pq] = r[1];
        *(float4*)&sp[hf][buf][2][pic][pq] = r[2];
        *(float4*)&sp[hf][buf][3][pic][pq] = r[3];
        vs[hf][buf][vrow][vq] = rv;
    };

    int buf = 0;
    prefetch(0); sts(0); __syncthreads();

    for (int c = 0; c < NC; c++){
        if (c + 1 < NC) prefetch(c + 1);
        #pragma unroll
        for (int ic = 0; ic < ICH; ic++){
            float2 SG = *(const float2*)&sp[hf][buf][0][ic][2*lane];
            float2 MS = *(const float2*)&sp[hf][buf][1][ic][2*lane];
            float2 WE = *(const float2*)&sp[hf][buf][2][ic][2*lane];
            float2 WW = *(const float2*)&sp[hf][buf][3][ic][2*lane];
            #pragma unroll
            for (int j = 0; j < 4; j++){
                float v = vs[hf][buf][4*wq + j][ic];
                float a0 = fmaf(v, SG.x, MS.x);
                float a1 = fmaf(v, SG.y, MS.y);
                float t0, t1;
                tanh2_fast(a0, a1, t0, t1);
                num[j][0] = fmaf(WE.x, t0, num[j][0]);
                den[j][0] = fmaf(WW.x, t0, den[j][0]);
                num[j][1] = fmaf(WE.y, t1, num[j][1]);
                den[j][1] = fmaf(WW.y, t1, den[j][1]);
            }
        }
        if (c + 1 < NC){ sts(buf ^ 1); __syncthreads(); buf ^= 1; }
    }

    // Combine halves: half 1 stores partials, half 0 adds them.
    __syncthreads();
    float* red = &sp[0][0][0][0][0];    // reuse SMEM (needs 2048 floats)
    if (hf == 1){
        #pragma unroll
        for (int j = 0; j < 4; j++){
            #pragma unroll
            for (int k = 0; k < 2; k++){
                red[txh*16 + j*2 + k]     = num[j][k];
                red[txh*16 + j*2 + k + 8] = den[j][k];
            }
        }
    }
    __syncthreads();
    if (hf == 0){
        #pragma unroll
        for (int j = 0; j < 4; j++){
            #pragma unroll
            for (int k = 0; k < 2; k++){
                num[j][k] += red[txh*16 + j*2 + k];
                den[j][k] += red[txh*16 + j*2 + k + 8];
            }
        }
    }
}

// ---------------------------------------------------------------------------
// Sensory pass: writes A[b,h], Dc[b,h] with all constants folded in.
// ---------------------------------------------------------------------------
__global__ __launch_bounds__(256) void k_sensory(
        const float* __restrict__ inp,
        const float* __restrict__ vleak, const float* __restrict__ gleak,
        const float* __restrict__ cm){
    __shared__ __align__(16) float sp[2][2][4][ICH][64];
    __shared__ float vs[2][2][16][ICH+1];

    const int h0 = blockIdx.x * 64;
    const int b0 = blockIdx.y * 16;
    const int tx = threadIdx.x;

    float num[4][2] = {}, den[4][2] = {};
    mainloop_core<I_SZ/2, I_SZ>(s_SG, s_MS, s_WE, s_WW, inp, h0, b0, tx,
                                num, den, sp, vs);

    if (tx < 128){
        const int lane = tx & 31;
        const int wq   = tx >> 5;
        #pragma unroll
        for (int k = 0; k < 2; k++){
            int h = h0 + 2*lane + k;
            float base_n = fmaf(gleak[h], vleak[h], g_CN[h]);
            float base_d = cm[h] + gleak[h] + g_CD[h];
            #pragma unroll
            for (int j = 0; j < 4; j++){
                int b = b0 + 4*wq + j;
                g_A [b*H_SZ + h] = num[j][k] + base_n;
                g_Dc[b*H_SZ + h] = den[j][k] + base_d;
            }
        }
    }
}

// ---------------------------------------------------------------------------
// One recurrent unfold.
// ---------------------------------------------------------------------------
__global__ __launch_bounds__(256) void k_step(const float* vext, float* voutext,
                                              int sel_in, int sel_out,
                                              const float* __restrict__ cm){
    const float* vin  = (sel_in  == 0) ? g_v0 : ((sel_in  == 1) ? g_v1 : vext);
    float*       vout = (sel_out == 0) ? g_v0 : ((sel_out == 1) ? g_v1 : voutext);

    __shared__ __align__(16) float sp[2][2][4][ICH][64];
    __shared__ float vs[2][2][16][ICH+1];

    const int h0 = blockIdx.x * 64;
    const int b0 = blockIdx.y * 16;
    const int tx = threadIdx.x;

    float num[4][2] = {}, den[4][2] = {};
    mainloop_core<H_SZ/2, H_SZ>(g_SG, g_MS, g_WE, g_WW, vin, h0, b0, tx,
                                num, den, sp, vs);

    if (tx < 128){
        const int lane = tx & 31;
        const int wq   = tx >> 5;
        #pragma unroll
        for (int k = 0; k < 2; k++){
            int h = h0 + 2*lane + k;
            float cmh = cm[h];
            #pragma unroll
            for (int j = 0; j < 4; j++){
                int b = b0 + 4*wq + j;
                float n = fmaf(cmh, vin[b*H_SZ + h], g_A[b*H_SZ + h]) + num[j][k];
                float d = g_Dc[b*H_SZ + h] + den[j][k];
                vout[b*H_SZ + h] = __fdividef(n, d + 1e-8f);
            }
        }
    }
}

extern "C" void kernel_launch(void* const* d_in, const int* in_sizes, int n_in,
                              void* d_out, int out_size){
    const float* inputs = (const float*)d_in[0];
    const float* state  = (const float*)d_in[1];
    const float* smu    = (const float*)d_in[2];
    const float* ssig   = (const float*)d_in[3];
    const float* sW     = (const float*)d_in[4];
    const float* serev  = (const float*)d_in[5];
    const float* mu     = (const float*)d_in[6];
    const float* sigma  = (const float*)d_in[7];
    const float* W      = (const float*)d_in[8];
    const float* erev   = (const float*)d_in[9];
    const float* vleak  = (const float*)d_in[10];
    const float* gleak  = (const float*)d_in[11];
    const float* cm     = (const float*)d_in[12];
    float* out = (float*)d_out;

    k_prep<<<((H_SZ+I_SZ)*H_SZ + 255)/256, 256>>>(mu, sigma, W, erev,
                                                  smu, ssig, sW, serev);
    k_colsum<<<H_SZ/32, 256>>>();

    dim3 grid(H_SZ/64, B_SZ/16);   // (8, 32) = 256 blocks, 256 threads each
    k_sensory<<<grid, 256>>>(inputs, vleak, gleak, cm);

    // 6 unfolds: state -> v0 -> v1 -> v0 -> v1 -> v0 -> out
    k_step<<<grid, 256>>>(state,   nullptr, 2, 0, cm);
    k_step<<<grid, 256>>>(nullptr, nullptr, 0, 1, cm);
    k_step<<<grid, 256>>>(nullptr, nullptr, 1, 0, cm);
    k_step<<<grid, 256>>>(nullptr, nullptr, 0, 1, cm);
    k_step<<<grid, 256>>>(nullptr, nullptr, 1, 0, cm);
    k_step<<<grid, 256>>>(nullptr, out,     0, 2, cm);
}